// round 13
// baseline (speedup 1.0000x reference)
#include <cuda_runtime.h>
#include <cuda_fp16.h>
#include <stdint.h>

// ---------------------------------------------------------------------------
// LightGCN: N=100000, D=64, E=1000000, 3 layers.
// out[0:ND] = E0 ; out[ND:2ND] = (E0 + x1 + x2 + x3)/4
//
// y = dinv (.) x stored fp16; x_l = di*s_l, y_l = di^2*s_l, s_l = sum y_{l-1}[src].
// R13: fill vectorized 4 edges/thread (hist recipe); E0->out copy moved into
// k_hist (streaming hides behind its atomic latency). Propagates = R12 exact.
// ---------------------------------------------------------------------------

#define MAXN 100000
#define MAXE 1000000
#define D    64

__device__ int    g_deg[MAXN];        // zero at load; re-zeroed in fill_init
__device__ float  g_dinv[MAXN];
__device__ float  g_rdi[MAXN];
__device__ int    g_off[MAXN + 1];
__device__ int    g_cursor[MAXN];
__device__ int    g_blocksums[128];
__device__ int    g_scanflag[128];
__device__ int    g_src[MAXE];
__device__ uint4  g_y0[MAXN * 8];
__device__ uint4  g_y1[MAXN * 8];
__device__ uint4  g_y2[MAXN * 8];

// ---------------------------------------------------------------------------
// Per-block dtype sniff: int64 indices < 2^31 have every odd 32-bit word == 0.
__device__ __forceinline__ bool block_is64(const int* __restrict__ p, int* s_flag) {
    if (threadIdx.x == 0) {
        int nz = 0;
        #pragma unroll 8
        for (int j = 1; j < 256; j += 2) nz += (p[j] != 0);
        *s_flag = (nz == 0);
    }
    __syncthreads();
    return *s_flag != 0;
}

// Histogram of destinations (4 edges/thread, first E/4 threads) + streaming
// copy out[0:NQ] = E0 (all threads). Block 0 also resets scan flags.
__global__ void k_hist_copy(const void* __restrict__ ei,
                            const float4* __restrict__ E0,
                            float4* __restrict__ out,
                            int E, int NQ) {
    __shared__ int s64;
    bool is64 = block_is64((const int*)ei, &s64);
    int i = blockIdx.x * blockDim.x + threadIdx.x;
    if (blockIdx.x == 0 && threadIdx.x < 128) g_scanflag[threadIdx.x] = 0;
    if (i < NQ) out[i] = E0[i];
    int base = i * 4;
    if (base >= E) return;
    int d0, d1, d2, d3;
    int n = E - base;
    if (is64) {
        const long long* p = (const long long*)ei + E + base;
        if (n >= 4) {
            longlong2 a = ((const longlong2*)p)[0];
            longlong2 b = ((const longlong2*)p)[1];
            d0 = (int)a.x; d1 = (int)a.y; d2 = (int)b.x; d3 = (int)b.y;
        } else {
            d0 = (int)p[0];
            d1 = (n > 1) ? (int)p[1] : -1;
            d2 = (n > 2) ? (int)p[2] : -1;
            d3 = -1;
        }
    } else {
        const int* p = (const int*)ei + E + base;
        if (n >= 4) {
            int4 a = *(const int4*)p;
            d0 = a.x; d1 = a.y; d2 = a.z; d3 = a.w;
        } else {
            d0 = p[0];
            d1 = (n > 1) ? p[1] : -1;
            d2 = (n > 2) ? p[2] : -1;
            d3 = -1;
        }
    }
    atomicAdd(&g_deg[d0], 1);
    if (d1 >= 0) atomicAdd(&g_deg[d1], 1);
    if (d2 >= 0) atomicAdd(&g_deg[d2], 1);
    if (d3 >= 0) atomicAdd(&g_deg[d3], 1);
}

// Single-pass exclusive scan of deg -> off (+ dinv/rdi). All 98 blocks resident.
__global__ void k_scan(int N, int E) {
    __shared__ int sh[1024];
    int tid = threadIdx.x;
    int bid = blockIdx.x;
    int i = bid * 1024 + tid;
    int v = (i < N) ? g_deg[i] : 0;
    if (i < N) {
        float fv = (float)v;
        g_dinv[i] = (v > 0) ? rsqrtf(fv) : 0.0f;
        g_rdi[i]  = (v > 0) ? sqrtf(fv)  : 0.0f;
    }
    sh[tid] = v;
    __syncthreads();
    #pragma unroll
    for (int ofs = 1; ofs < 1024; ofs <<= 1) {
        int t = (tid >= ofs) ? sh[tid - ofs] : 0;
        __syncthreads();
        sh[tid] += t;
        __syncthreads();
    }
    int incl = sh[tid];
    if (tid == 1023) {
        g_blocksums[bid] = incl;
        __threadfence();
        ((volatile int*)g_scanflag)[bid] = 1;
    }
    __syncthreads();
    int part = 0;
    if (tid < bid) {
        while (((volatile int*)g_scanflag)[tid] == 0) {}
        __threadfence();
        part = g_blocksums[tid];
    }
    sh[tid] = part;
    __syncthreads();
    #pragma unroll
    for (int ofs = 512; ofs > 0; ofs >>= 1) {
        if (tid < ofs) sh[tid] += sh[tid + ofs];
        __syncthreads();
    }
    int base = sh[0];
    if (i < N) {
        int o = base + incl - v;
        g_off[i] = o;
        g_cursor[i] = o;
    }
    if (i == 0) g_off[N] = E;
}

// Fused: vectorized CSR fill (4 edges/thread, first E/4 threads) + y0 init
// + deg reset.
__global__ void k_fill_init(const void* __restrict__ ei,
                            const float4* __restrict__ E0,
                            int E, int NQ, int N) {
    __shared__ int s64;
    bool is64 = block_is64((const int*)ei, &s64);
    int i = blockIdx.x * blockDim.x + threadIdx.x;
    if (i < N) g_deg[i] = 0;
    int base = i * 4;
    if (base < E) {
        int s0, s1, s2, s3, d0, d1, d2, d3;
        int n = E - base;
        if (is64) {
            const long long* ps = (const long long*)ei + base;
            const long long* pd = (const long long*)ei + E + base;
            if (n >= 4) {
                longlong2 sa = ((const longlong2*)ps)[0];
                longlong2 sb = ((const longlong2*)ps)[1];
                longlong2 da = ((const longlong2*)pd)[0];
                longlong2 db = ((const longlong2*)pd)[1];
                s0 = (int)sa.x; s1 = (int)sa.y; s2 = (int)sb.x; s3 = (int)sb.y;
                d0 = (int)da.x; d1 = (int)da.y; d2 = (int)db.x; d3 = (int)db.y;
            } else {
                s0 = (int)ps[0]; d0 = (int)pd[0];
                s1 = (n > 1) ? (int)ps[1] : 0; d1 = (n > 1) ? (int)pd[1] : -1;
                s2 = (n > 2) ? (int)ps[2] : 0; d2 = (n > 2) ? (int)pd[2] : -1;
                s3 = 0; d3 = -1;
            }
        } else {
            const int* ps = (const int*)ei + base;
            const int* pd = (const int*)ei + E + base;
            if (n >= 4) {
                int4 sa = *(const int4*)ps;
                int4 da = *(const int4*)pd;
                s0 = sa.x; s1 = sa.y; s2 = sa.z; s3 = sa.w;
                d0 = da.x; d1 = da.y; d2 = da.z; d3 = da.w;
            } else {
                s0 = ps[0]; d0 = pd[0];
                s1 = (n > 1) ? ps[1] : 0; d1 = (n > 1) ? pd[1] : -1;
                s2 = (n > 2) ? ps[2] : 0; d2 = (n > 2) ? pd[2] : -1;
                s3 = 0; d3 = -1;
            }
        }
        int p0 = atomicAdd(&g_cursor[d0], 1);
        int p1 = (d1 >= 0) ? atomicAdd(&g_cursor[d1], 1) : 0;
        int p2 = (d2 >= 0) ? atomicAdd(&g_cursor[d2], 1) : 0;
        int p3 = (d3 >= 0) ? atomicAdd(&g_cursor[d3], 1) : 0;
        g_src[p0] = s0;
        if (d1 >= 0) g_src[p1] = s1;
        if (d2 >= 0) g_src[p2] = s2;
        if (d3 >= 0) g_src[p3] = s3;
    }
    if (i < NQ) {
        float4 v = E0[i];
        float di = g_dinv[i >> 4];
        uint2 w;
        __half2* hw = (__half2*)&w;
        hw[0] = __floats2half2_rn(v.x * di, v.y * di);
        hw[1] = __floats2half2_rn(v.z * di, v.w * di);
        ((uint2*)g_y0)[i] = w;
    }
}

// Mid-layer propagate (R10/R12 exact): 8 lanes/node, 32 nodes/block,
// 2-edge unroll, 2 HADD2 banks, 8 blocks/SM (64 warps).
__global__ void __launch_bounds__(256, 8)
k_propagate(const uint4* __restrict__ y, uint4* __restrict__ yn, int N) {
    int node = blockIdx.x * 32 + threadIdx.y;
    if (node >= N) return;
    int t = threadIdx.x;  // 0..7
    int beg = g_off[node];
    int end = g_off[node + 1];
    __half2 z = __float2half2_rn(0.f);
    __half2 a0[4] = {z, z, z, z};
    __half2 a1[4] = {z, z, z, z};
    int e = beg;
    for (; e + 1 < end; e += 2) {
        int sa = g_src[e];
        int sb = g_src[e + 1];
        uint4 ua = y[sa * 8 + t];
        uint4 ub = y[sb * 8 + t];
        const __half2* ha = (const __half2*)&ua;
        const __half2* hb = (const __half2*)&ub;
        #pragma unroll
        for (int j = 0; j < 4; j++) {
            a0[j] = __hadd2(a0[j], ha[j]);
            a1[j] = __hadd2(a1[j], hb[j]);
        }
    }
    if (e < end) {
        uint4 ua = y[g_src[e] * 8 + t];
        const __half2* ha = (const __half2*)&ua;
        #pragma unroll
        for (int j = 0; j < 4; j++) a0[j] = __hadd2(a0[j], ha[j]);
    }
    float di2 = g_dinv[node];
    di2 *= di2;
    uint4 w;
    __half2* hw = (__half2*)&w;
    #pragma unroll
    for (int j = 0; j < 4; j++) {
        float2 f0 = __half22float2(a0[j]);
        float2 f1 = __half22float2(a1[j]);
        hw[j] = __floats2half2_rn(di2 * (f0.x + f1.x), di2 * (f0.y + f1.y));
    }
    yn[node * 8 + t] = w;
}

// Final layer fused with output (R12 exact): 2-bank HADD2 gather, fp32 finalize.
__global__ void __launch_bounds__(256, 8)
k_propagate_last(const uint4* __restrict__ y2,
                 const uint4* __restrict__ y1,
                 const float4* __restrict__ E0,
                 float4* __restrict__ out, int N, int NQ) {
    int node = blockIdx.x * 32 + threadIdx.y;
    if (node >= N) return;
    int t = threadIdx.x;
    int beg = g_off[node];
    int end = g_off[node + 1];
    __half2 z = __float2half2_rn(0.f);
    __half2 a0[4] = {z, z, z, z};
    __half2 a1[4] = {z, z, z, z};
    int e = beg;
    for (; e + 1 < end; e += 2) {
        int sa = g_src[e];
        int sb = g_src[e + 1];
        uint4 ua = y2[sa * 8 + t];
        uint4 ub = y2[sb * 8 + t];
        const __half2* ha = (const __half2*)&ua;
        const __half2* hb = (const __half2*)&ub;
        #pragma unroll
        for (int j = 0; j < 4; j++) {
            a0[j] = __hadd2(a0[j], ha[j]);
            a1[j] = __hadd2(a1[j], hb[j]);
        }
    }
    if (e < end) {
        uint4 ua = y2[g_src[e] * 8 + t];
        const __half2* ha = (const __half2*)&ua;
        #pragma unroll
        for (int j = 0; j < 4; j++) a0[j] = __hadd2(a0[j], ha[j]);
    }
    float di  = g_dinv[node];
    float rdi = g_rdi[node];

    uint4 u1 = y1[node * 8 + t];
    uint4 u2 = y2[node * 8 + t];
    const __half2* h1 = (const __half2*)&u1;
    const __half2* h2 = (const __half2*)&u2;

    int o4 = node * 16 + t * 2;
    float4 e0a = E0[o4], e0b = E0[o4 + 1];
    float rr[8];
    #pragma unroll
    for (int j = 0; j < 4; j++) {
        float2 f0 = __half22float2(a0[j]);
        float2 f1 = __half22float2(a1[j]);
        float2 g1 = __half22float2(h1[j]);
        float2 g2 = __half22float2(h2[j]);
        rr[2 * j]     = rdi * (g1.x + g2.x) + di * (f0.x + f1.x);
        rr[2 * j + 1] = rdi * (g1.y + g2.y) + di * (f0.y + f1.y);
    }
    float4 r0, r1;
    r0.x = 0.25f * (e0a.x + rr[0]);
    r0.y = 0.25f * (e0a.y + rr[1]);
    r0.z = 0.25f * (e0a.z + rr[2]);
    r0.w = 0.25f * (e0a.w + rr[3]);
    r1.x = 0.25f * (e0b.x + rr[4]);
    r1.y = 0.25f * (e0b.y + rr[5]);
    r1.z = 0.25f * (e0b.z + rr[6]);
    r1.w = 0.25f * (e0b.w + rr[7]);
    out[NQ + o4] = r0;
    out[NQ + o4 + 1] = r1;
}

// ---------------------------------------------------------------------------

extern "C" void kernel_launch(void* const* d_in, const int* in_sizes, int n_in,
                              void* d_out, int out_size) {
    const float4* E0 = (const float4*)d_in[0];
    const void*   ei = d_in[1];
    float4*       out = (float4*)d_out;

    int N  = in_sizes[0] / D;   // 100000
    int E  = in_sizes[1] / 2;   // 1000000
    int NQ = N * 16;

    void *p0 = nullptr, *p1 = nullptr, *p2 = nullptr;
    cudaGetSymbolAddress(&p0, g_y0);
    cudaGetSymbolAddress(&p1, g_y1);
    cudaGetSymbolAddress(&p2, g_y2);
    uint4* y0 = (uint4*)p0;
    uint4* y1 = (uint4*)p1;
    uint4* y2 = (uint4*)p2;

    const int T = 256;
    int nb_scan = (N + 1023) / 1024;
    int nb_big  = (NQ + T - 1) / T;   // covers NQ threads (also >= E/4, N)

    k_hist_copy<<<nb_big, T>>>(ei, E0, out, E, NQ);
    k_scan<<<nb_scan, 1024>>>(N, E);
    k_fill_init<<<nb_big, T>>>(ei, E0, E, NQ, N);

    dim3 pb(8, 32);
    int  pg = (N + 31) / 32;
    k_propagate<<<pg, pb>>>(y0, y1, N);
    k_propagate<<<pg, pb>>>(y1, y2, N);
    k_propagate_last<<<pg, pb>>>(y2, y1, E0, out, N, NQ);
}

// round 14
// speedup vs baseline: 1.0373x; 1.0373x over previous
#include <cuda_runtime.h>
#include <cuda_fp16.h>
#include <stdint.h>

// ---------------------------------------------------------------------------
// LightGCN: N=100000, D=64, E=1000000, 3 layers.
// out[0:ND] = E0 ; out[ND:2ND] = (E0 + x1 + x2 + x3)/4
//
// y = dinv (.) x stored fp16; x_l = di*s_l, y_l = di^2*s_l, s_l = sum y_{l-1}[src].
// R14 = R12 exact, except the out[0:NQ]=E0 copy moves from k_fill_init into
// k_propagate_last (which already holds E0 in registers -> free stores).
// ---------------------------------------------------------------------------

#define MAXN 100000
#define MAXE 1000000
#define D    64

__device__ int    g_deg[MAXN];        // zero at load; re-zeroed in fill_init
__device__ float  g_dinv[MAXN];
__device__ float  g_rdi[MAXN];
__device__ int    g_off[MAXN + 1];
__device__ int    g_cursor[MAXN];
__device__ int    g_blocksums[128];
__device__ int    g_scanflag[128];
__device__ int    g_src[MAXE];
__device__ uint4  g_y0[MAXN * 8];
__device__ uint4  g_y1[MAXN * 8];
__device__ uint4  g_y2[MAXN * 8];

// ---------------------------------------------------------------------------
// Per-block dtype sniff: int64 indices < 2^31 have every odd 32-bit word == 0.
__device__ __forceinline__ bool block_is64(const int* __restrict__ p, int* s_flag) {
    if (threadIdx.x == 0) {
        int nz = 0;
        #pragma unroll 8
        for (int j = 1; j < 256; j += 2) nz += (p[j] != 0);
        *s_flag = (nz == 0);
    }
    __syncthreads();
    return *s_flag != 0;
}

// Histogram of destinations, 4 edges per thread. Block 0 also resets scan flags.
__global__ void k_hist(const void* __restrict__ ei, int E) {
    __shared__ int s64;
    bool is64 = block_is64((const int*)ei, &s64);
    if (blockIdx.x == 0 && threadIdx.x < 128) g_scanflag[threadIdx.x] = 0;
    int base = (blockIdx.x * blockDim.x + threadIdx.x) * 4;
    if (base >= E) return;
    int d0, d1, d2, d3;
    int n = E - base;
    if (is64) {
        const long long* p = (const long long*)ei + E + base;
        if (n >= 4) {
            longlong2 a = ((const longlong2*)p)[0];
            longlong2 b = ((const longlong2*)p)[1];
            d0 = (int)a.x; d1 = (int)a.y; d2 = (int)b.x; d3 = (int)b.y;
        } else {
            d0 = (int)p[0];
            d1 = (n > 1) ? (int)p[1] : -1;
            d2 = (n > 2) ? (int)p[2] : -1;
            d3 = -1;
        }
    } else {
        const int* p = (const int*)ei + E + base;
        if (n >= 4) {
            int4 a = *(const int4*)p;
            d0 = a.x; d1 = a.y; d2 = a.z; d3 = a.w;
        } else {
            d0 = p[0];
            d1 = (n > 1) ? p[1] : -1;
            d2 = (n > 2) ? p[2] : -1;
            d3 = -1;
        }
    }
    atomicAdd(&g_deg[d0], 1);
    if (d1 >= 0) atomicAdd(&g_deg[d1], 1);
    if (d2 >= 0) atomicAdd(&g_deg[d2], 1);
    if (d3 >= 0) atomicAdd(&g_deg[d3], 1);
}

// Single-pass exclusive scan of deg -> off (+ dinv/rdi). All 98 blocks resident.
__global__ void k_scan(int N, int E) {
    __shared__ int sh[1024];
    int tid = threadIdx.x;
    int bid = blockIdx.x;
    int i = bid * 1024 + tid;
    int v = (i < N) ? g_deg[i] : 0;
    if (i < N) {
        float fv = (float)v;
        g_dinv[i] = (v > 0) ? rsqrtf(fv) : 0.0f;
        g_rdi[i]  = (v > 0) ? sqrtf(fv)  : 0.0f;
    }
    sh[tid] = v;
    __syncthreads();
    #pragma unroll
    for (int ofs = 1; ofs < 1024; ofs <<= 1) {
        int t = (tid >= ofs) ? sh[tid - ofs] : 0;
        __syncthreads();
        sh[tid] += t;
        __syncthreads();
    }
    int incl = sh[tid];
    if (tid == 1023) {
        g_blocksums[bid] = incl;
        __threadfence();
        ((volatile int*)g_scanflag)[bid] = 1;
    }
    __syncthreads();
    int part = 0;
    if (tid < bid) {
        while (((volatile int*)g_scanflag)[tid] == 0) {}
        __threadfence();
        part = g_blocksums[tid];
    }
    sh[tid] = part;
    __syncthreads();
    #pragma unroll
    for (int ofs = 512; ofs > 0; ofs >>= 1) {
        if (tid < ofs) sh[tid] += sh[tid + ofs];
        __syncthreads();
    }
    int base = sh[0];
    if (i < N) {
        int o = base + incl - v;
        g_off[i] = o;
        g_cursor[i] = o;
    }
    if (i == 0) g_off[N] = E;
}

// Fused: CSR fill (atomic cursor, 1 edge/thread) + y0 init + deg reset.
__global__ void k_fill_init(const void* __restrict__ ei,
                            const float4* __restrict__ E0,
                            int E, int NQ, int N) {
    __shared__ int s64;
    bool is64 = block_is64((const int*)ei, &s64);
    int i = blockIdx.x * blockDim.x + threadIdx.x;
    if (i < N) g_deg[i] = 0;
    if (i < E) {
        int s, d;
        if (is64) {
            s = (int)((const long long*)ei)[i];
            d = (int)((const long long*)ei)[E + i];
        } else {
            s = ((const int*)ei)[i];
            d = ((const int*)ei)[E + i];
        }
        int pos = atomicAdd(&g_cursor[d], 1);
        g_src[pos] = s;
    }
    if (i < NQ) {
        float4 v = E0[i];
        float di = g_dinv[i >> 4];
        uint2 w;
        __half2* hw = (__half2*)&w;
        hw[0] = __floats2half2_rn(v.x * di, v.y * di);
        hw[1] = __floats2half2_rn(v.z * di, v.w * di);
        ((uint2*)g_y0)[i] = w;
    }
}

// Mid-layer propagate (R10/R12 exact): 8 lanes/node, 32 nodes/block,
// 2-edge unroll, 2 HADD2 banks, 8 blocks/SM (64 warps).
__global__ void __launch_bounds__(256, 8)
k_propagate(const uint4* __restrict__ y, uint4* __restrict__ yn, int N) {
    int node = blockIdx.x * 32 + threadIdx.y;
    if (node >= N) return;
    int t = threadIdx.x;  // 0..7
    int beg = g_off[node];
    int end = g_off[node + 1];
    __half2 z = __float2half2_rn(0.f);
    __half2 a0[4] = {z, z, z, z};
    __half2 a1[4] = {z, z, z, z};
    int e = beg;
    for (; e + 1 < end; e += 2) {
        int sa = g_src[e];
        int sb = g_src[e + 1];
        uint4 ua = y[sa * 8 + t];
        uint4 ub = y[sb * 8 + t];
        const __half2* ha = (const __half2*)&ua;
        const __half2* hb = (const __half2*)&ub;
        #pragma unroll
        for (int j = 0; j < 4; j++) {
            a0[j] = __hadd2(a0[j], ha[j]);
            a1[j] = __hadd2(a1[j], hb[j]);
        }
    }
    if (e < end) {
        uint4 ua = y[g_src[e] * 8 + t];
        const __half2* ha = (const __half2*)&ua;
        #pragma unroll
        for (int j = 0; j < 4; j++) a0[j] = __hadd2(a0[j], ha[j]);
    }
    float di2 = g_dinv[node];
    di2 *= di2;
    uint4 w;
    __half2* hw = (__half2*)&w;
    #pragma unroll
    for (int j = 0; j < 4; j++) {
        float2 f0 = __half22float2(a0[j]);
        float2 f1 = __half22float2(a1[j]);
        hw[j] = __floats2half2_rn(di2 * (f0.x + f1.x), di2 * (f0.y + f1.y));
    }
    yn[node * 8 + t] = w;
}

// Final layer fused with output: 2-bank HADD2 gather, fp32 finalize.
// Writes BOTH halves of out: out[o]=E0 (free, already in regs) and
// out[NQ+o]=0.25*(E0 + (y1+y2)*rdi + di*s3).
__global__ void __launch_bounds__(256, 8)
k_propagate_last(const uint4* __restrict__ y2,
                 const uint4* __restrict__ y1,
                 const float4* __restrict__ E0,
                 float4* __restrict__ out, int N, int NQ) {
    int node = blockIdx.x * 32 + threadIdx.y;
    if (node >= N) return;
    int t = threadIdx.x;
    int beg = g_off[node];
    int end = g_off[node + 1];
    __half2 z = __float2half2_rn(0.f);
    __half2 a0[4] = {z, z, z, z};
    __half2 a1[4] = {z, z, z, z};
    int e = beg;
    for (; e + 1 < end; e += 2) {
        int sa = g_src[e];
        int sb = g_src[e + 1];
        uint4 ua = y2[sa * 8 + t];
        uint4 ub = y2[sb * 8 + t];
        const __half2* ha = (const __half2*)&ua;
        const __half2* hb = (const __half2*)&ub;
        #pragma unroll
        for (int j = 0; j < 4; j++) {
            a0[j] = __hadd2(a0[j], ha[j]);
            a1[j] = __hadd2(a1[j], hb[j]);
        }
    }
    if (e < end) {
        uint4 ua = y2[g_src[e] * 8 + t];
        const __half2* ha = (const __half2*)&ua;
        #pragma unroll
        for (int j = 0; j < 4; j++) a0[j] = __hadd2(a0[j], ha[j]);
    }
    float di  = g_dinv[node];
    float rdi = g_rdi[node];

    uint4 u1 = y1[node * 8 + t];
    uint4 u2 = y2[node * 8 + t];
    const __half2* h1 = (const __half2*)&u1;
    const __half2* h2 = (const __half2*)&u2;

    int o4 = node * 16 + t * 2;
    float4 e0a = E0[o4], e0b = E0[o4 + 1];
    out[o4]     = e0a;   // first half of out: passthrough, data already loaded
    out[o4 + 1] = e0b;
    float rr[8];
    #pragma unroll
    for (int j = 0; j < 4; j++) {
        float2 f0 = __half22float2(a0[j]);
        float2 f1 = __half22float2(a1[j]);
        float2 g1 = __half22float2(h1[j]);
        float2 g2 = __half22float2(h2[j]);
        rr[2 * j]     = rdi * (g1.x + g2.x) + di * (f0.x + f1.x);
        rr[2 * j + 1] = rdi * (g1.y + g2.y) + di * (f0.y + f1.y);
    }
    float4 r0, r1;
    r0.x = 0.25f * (e0a.x + rr[0]);
    r0.y = 0.25f * (e0a.y + rr[1]);
    r0.z = 0.25f * (e0a.z + rr[2]);
    r0.w = 0.25f * (e0a.w + rr[3]);
    r1.x = 0.25f * (e0b.x + rr[4]);
    r1.y = 0.25f * (e0b.y + rr[5]);
    r1.z = 0.25f * (e0b.z + rr[6]);
    r1.w = 0.25f * (e0b.w + rr[7]);
    out[NQ + o4] = r0;
    out[NQ + o4 + 1] = r1;
}

// ---------------------------------------------------------------------------

extern "C" void kernel_launch(void* const* d_in, const int* in_sizes, int n_in,
                              void* d_out, int out_size) {
    const float4* E0 = (const float4*)d_in[0];
    const void*   ei = d_in[1];
    float4*       out = (float4*)d_out;

    int N  = in_sizes[0] / D;   // 100000
    int E  = in_sizes[1] / 2;   // 1000000
    int NQ = N * 16;

    void *p0 = nullptr, *p1 = nullptr, *p2 = nullptr;
    cudaGetSymbolAddress(&p0, g_y0);
    cudaGetSymbolAddress(&p1, g_y1);
    cudaGetSymbolAddress(&p2, g_y2);
    uint4* y0 = (uint4*)p0;
    uint4* y1 = (uint4*)p1;
    uint4* y2 = (uint4*)p2;

    const int T = 256;
    int nb_scan = (N + 1023) / 1024;
    int nb_hist = ((E + 3) / 4 + T - 1) / T;

    k_hist<<<nb_hist, T>>>(ei, E);
    k_scan<<<nb_scan, 1024>>>(N, E);
    k_fill_init<<<(NQ + T - 1) / T, T>>>(ei, E0, E, NQ, N);

    dim3 pb(8, 32);
    int  pg = (N + 31) / 32;
    k_propagate<<<pg, pb>>>(y0, y1, N);
    k_propagate<<<pg, pb>>>(y1, y2, N);
    k_propagate_last<<<pg, pb>>>(y2, y1, E0, out, N, NQ);
}

// round 15
// speedup vs baseline: 1.0811x; 1.0422x over previous
#include <cuda_runtime.h>
#include <cuda_fp16.h>
#include <stdint.h>

// ---------------------------------------------------------------------------
// LightGCN: N=100000, D=64, E=1000000, 3 layers.
// out[0:ND] = E0 ; out[ND:2ND] = (E0 + x1 + x2 + x3)/4
//
// y = dinv (.) x stored fp16; x_l = di*s_l, y_l = di^2*s_l, s_l = sum y_{l-1}[src].
// R15 = R12 exact (best measured, 96.7us), except the three propagate kernels
// are persistent grid-stride (grid = 148*8 blocks) to remove wave quantization
// (3125 blocks / 1184 resident = 2.64 waves -> fractional-tail idle).
// ---------------------------------------------------------------------------

#define MAXN 100000
#define MAXE 1000000
#define D    64
#define PROP_GRID 1184   // 148 SMs x 8 blocks/SM resident

__device__ int    g_deg[MAXN];        // zero at load; re-zeroed in fill_init
__device__ float  g_dinv[MAXN];
__device__ float  g_rdi[MAXN];
__device__ int    g_off[MAXN + 1];
__device__ int    g_cursor[MAXN];
__device__ int    g_blocksums[128];
__device__ int    g_scanflag[128];
__device__ int    g_src[MAXE];
__device__ uint4  g_y0[MAXN * 8];
__device__ uint4  g_y1[MAXN * 8];
__device__ uint4  g_y2[MAXN * 8];

// ---------------------------------------------------------------------------
// Per-block dtype sniff: int64 indices < 2^31 have every odd 32-bit word == 0.
__device__ __forceinline__ bool block_is64(const int* __restrict__ p, int* s_flag) {
    if (threadIdx.x == 0) {
        int nz = 0;
        #pragma unroll 8
        for (int j = 1; j < 256; j += 2) nz += (p[j] != 0);
        *s_flag = (nz == 0);
    }
    __syncthreads();
    return *s_flag != 0;
}

// Histogram of destinations, 4 edges per thread. Block 0 also resets scan flags.
__global__ void k_hist(const void* __restrict__ ei, int E) {
    __shared__ int s64;
    bool is64 = block_is64((const int*)ei, &s64);
    if (blockIdx.x == 0 && threadIdx.x < 128) g_scanflag[threadIdx.x] = 0;
    int base = (blockIdx.x * blockDim.x + threadIdx.x) * 4;
    if (base >= E) return;
    int d0, d1, d2, d3;
    int n = E - base;
    if (is64) {
        const long long* p = (const long long*)ei + E + base;
        if (n >= 4) {
            longlong2 a = ((const longlong2*)p)[0];
            longlong2 b = ((const longlong2*)p)[1];
            d0 = (int)a.x; d1 = (int)a.y; d2 = (int)b.x; d3 = (int)b.y;
        } else {
            d0 = (int)p[0];
            d1 = (n > 1) ? (int)p[1] : -1;
            d2 = (n > 2) ? (int)p[2] : -1;
            d3 = -1;
        }
    } else {
        const int* p = (const int*)ei + E + base;
        if (n >= 4) {
            int4 a = *(const int4*)p;
            d0 = a.x; d1 = a.y; d2 = a.z; d3 = a.w;
        } else {
            d0 = p[0];
            d1 = (n > 1) ? p[1] : -1;
            d2 = (n > 2) ? p[2] : -1;
            d3 = -1;
        }
    }
    atomicAdd(&g_deg[d0], 1);
    if (d1 >= 0) atomicAdd(&g_deg[d1], 1);
    if (d2 >= 0) atomicAdd(&g_deg[d2], 1);
    if (d3 >= 0) atomicAdd(&g_deg[d3], 1);
}

// Single-pass exclusive scan of deg -> off (+ dinv/rdi). All 98 blocks resident.
__global__ void k_scan(int N, int E) {
    __shared__ int sh[1024];
    int tid = threadIdx.x;
    int bid = blockIdx.x;
    int i = bid * 1024 + tid;
    int v = (i < N) ? g_deg[i] : 0;
    if (i < N) {
        float fv = (float)v;
        g_dinv[i] = (v > 0) ? rsqrtf(fv) : 0.0f;
        g_rdi[i]  = (v > 0) ? sqrtf(fv)  : 0.0f;
    }
    sh[tid] = v;
    __syncthreads();
    #pragma unroll
    for (int ofs = 1; ofs < 1024; ofs <<= 1) {
        int t = (tid >= ofs) ? sh[tid - ofs] : 0;
        __syncthreads();
        sh[tid] += t;
        __syncthreads();
    }
    int incl = sh[tid];
    if (tid == 1023) {
        g_blocksums[bid] = incl;
        __threadfence();
        ((volatile int*)g_scanflag)[bid] = 1;
    }
    __syncthreads();
    int part = 0;
    if (tid < bid) {
        while (((volatile int*)g_scanflag)[tid] == 0) {}
        __threadfence();
        part = g_blocksums[tid];
    }
    sh[tid] = part;
    __syncthreads();
    #pragma unroll
    for (int ofs = 512; ofs > 0; ofs >>= 1) {
        if (tid < ofs) sh[tid] += sh[tid + ofs];
        __syncthreads();
    }
    int base = sh[0];
    if (i < N) {
        int o = base + incl - v;
        g_off[i] = o;
        g_cursor[i] = o;
    }
    if (i == 0) g_off[N] = E;
}

// Fused: CSR fill (atomic cursor, 1 edge/thread) + out[0:NQ]=E0 + y0 init
// + deg reset. (R12 exact arrangement.)
__global__ void k_fill_init(const void* __restrict__ ei,
                            const float4* __restrict__ E0,
                            float4* __restrict__ out,
                            int E, int NQ, int N) {
    __shared__ int s64;
    bool is64 = block_is64((const int*)ei, &s64);
    int i = blockIdx.x * blockDim.x + threadIdx.x;
    if (i < N) g_deg[i] = 0;
    if (i < E) {
        int s, d;
        if (is64) {
            s = (int)((const long long*)ei)[i];
            d = (int)((const long long*)ei)[E + i];
        } else {
            s = ((const int*)ei)[i];
            d = ((const int*)ei)[E + i];
        }
        int pos = atomicAdd(&g_cursor[d], 1);
        g_src[pos] = s;
    }
    if (i < NQ) {
        float4 v = E0[i];
        out[i] = v;
        float di = g_dinv[i >> 4];
        uint2 w;
        __half2* hw = (__half2*)&w;
        hw[0] = __floats2half2_rn(v.x * di, v.y * di);
        hw[1] = __floats2half2_rn(v.z * di, v.w * di);
        ((uint2*)g_y0)[i] = w;
    }
}

// Mid-layer propagate: persistent grid-stride over node slots; inner body is
// R10/R12 exact (8 lanes/node, 2-edge unroll, 2 HADD2 banks, 8 blocks/SM).
__global__ void __launch_bounds__(256, 8)
k_propagate(const uint4* __restrict__ y, uint4* __restrict__ yn, int N) {
    int t = threadIdx.x;  // 0..7
    int stride = gridDim.x * 32;
    for (int node = blockIdx.x * 32 + threadIdx.y; node < N; node += stride) {
        int beg = g_off[node];
        int end = g_off[node + 1];
        __half2 z = __float2half2_rn(0.f);
        __half2 a0[4] = {z, z, z, z};
        __half2 a1[4] = {z, z, z, z};
        int e = beg;
        for (; e + 1 < end; e += 2) {
            int sa = g_src[e];
            int sb = g_src[e + 1];
            uint4 ua = y[sa * 8 + t];
            uint4 ub = y[sb * 8 + t];
            const __half2* ha = (const __half2*)&ua;
            const __half2* hb = (const __half2*)&ub;
            #pragma unroll
            for (int j = 0; j < 4; j++) {
                a0[j] = __hadd2(a0[j], ha[j]);
                a1[j] = __hadd2(a1[j], hb[j]);
            }
        }
        if (e < end) {
            uint4 ua = y[g_src[e] * 8 + t];
            const __half2* ha = (const __half2*)&ua;
            #pragma unroll
            for (int j = 0; j < 4; j++) a0[j] = __hadd2(a0[j], ha[j]);
        }
        float di2 = g_dinv[node];
        di2 *= di2;
        uint4 w;
        __half2* hw = (__half2*)&w;
        #pragma unroll
        for (int j = 0; j < 4; j++) {
            float2 f0 = __half22float2(a0[j]);
            float2 f1 = __half22float2(a1[j]);
            hw[j] = __floats2half2_rn(di2 * (f0.x + f1.x), di2 * (f0.y + f1.y));
        }
        yn[node * 8 + t] = w;
    }
}

// Final layer fused with output: persistent grid-stride; body = R12 exact
// (2-bank HADD2 gather, fp32 finalize). out = 0.25*(E0 + (y1+y2)*rdi + di*s3).
__global__ void __launch_bounds__(256, 8)
k_propagate_last(const uint4* __restrict__ y2,
                 const uint4* __restrict__ y1,
                 const float4* __restrict__ E0,
                 float4* __restrict__ out, int N, int NQ) {
    int t = threadIdx.x;
    int stride = gridDim.x * 32;
    for (int node = blockIdx.x * 32 + threadIdx.y; node < N; node += stride) {
        int beg = g_off[node];
        int end = g_off[node + 1];
        __half2 z = __float2half2_rn(0.f);
        __half2 a0[4] = {z, z, z, z};
        __half2 a1[4] = {z, z, z, z};
        int e = beg;
        for (; e + 1 < end; e += 2) {
            int sa = g_src[e];
            int sb = g_src[e + 1];
            uint4 ua = y2[sa * 8 + t];
            uint4 ub = y2[sb * 8 + t];
            const __half2* ha = (const __half2*)&ua;
            const __half2* hb = (const __half2*)&ub;
            #pragma unroll
            for (int j = 0; j < 4; j++) {
                a0[j] = __hadd2(a0[j], ha[j]);
                a1[j] = __hadd2(a1[j], hb[j]);
            }
        }
        if (e < end) {
            uint4 ua = y2[g_src[e] * 8 + t];
            const __half2* ha = (const __half2*)&ua;
            #pragma unroll
            for (int j = 0; j < 4; j++) a0[j] = __hadd2(a0[j], ha[j]);
        }
        float di  = g_dinv[node];
        float rdi = g_rdi[node];

        uint4 u1 = y1[node * 8 + t];
        uint4 u2 = y2[node * 8 + t];
        const __half2* h1 = (const __half2*)&u1;
        const __half2* h2 = (const __half2*)&u2;

        int o4 = node * 16 + t * 2;
        float4 e0a = E0[o4], e0b = E0[o4 + 1];
        float rr[8];
        #pragma unroll
        for (int j = 0; j < 4; j++) {
            float2 f0 = __half22float2(a0[j]);
            float2 f1 = __half22float2(a1[j]);
            float2 g1 = __half22float2(h1[j]);
            float2 g2 = __half22float2(h2[j]);
            rr[2 * j]     = rdi * (g1.x + g2.x) + di * (f0.x + f1.x);
            rr[2 * j + 1] = rdi * (g1.y + g2.y) + di * (f0.y + f1.y);
        }
        float4 r0, r1;
        r0.x = 0.25f * (e0a.x + rr[0]);
        r0.y = 0.25f * (e0a.y + rr[1]);
        r0.z = 0.25f * (e0a.z + rr[2]);
        r0.w = 0.25f * (e0a.w + rr[3]);
        r1.x = 0.25f * (e0b.x + rr[4]);
        r1.y = 0.25f * (e0b.y + rr[5]);
        r1.z = 0.25f * (e0b.z + rr[6]);
        r1.w = 0.25f * (e0b.w + rr[7]);
        out[NQ + o4] = r0;
        out[NQ + o4 + 1] = r1;
    }
}

// ---------------------------------------------------------------------------

extern "C" void kernel_launch(void* const* d_in, const int* in_sizes, int n_in,
                              void* d_out, int out_size) {
    const float4* E0 = (const float4*)d_in[0];
    const void*   ei = d_in[1];
    float4*       out = (float4*)d_out;

    int N  = in_sizes[0] / D;   // 100000
    int E  = in_sizes[1] / 2;   // 1000000
    int NQ = N * 16;

    void *p0 = nullptr, *p1 = nullptr, *p2 = nullptr;
    cudaGetSymbolAddress(&p0, g_y0);
    cudaGetSymbolAddress(&p1, g_y1);
    cudaGetSymbolAddress(&p2, g_y2);
    uint4* y0 = (uint4*)p0;
    uint4* y1 = (uint4*)p1;
    uint4* y2 = (uint4*)p2;

    const int T = 256;
    int nb_scan = (N + 1023) / 1024;
    int nb_hist = ((E + 3) / 4 + T - 1) / T;

    k_hist<<<nb_hist, T>>>(ei, E);
    k_scan<<<nb_scan, 1024>>>(N, E);
    k_fill_init<<<(NQ + T - 1) / T, T>>>(ei, E0, out, E, NQ, N);

    dim3 pb(8, 32);
    int  pg_full = (N + 31) / 32;
    int  pg = pg_full < PROP_GRID ? pg_full : PROP_GRID;
    k_propagate<<<pg, pb>>>(y0, y1, N);
    k_propagate<<<pg, pb>>>(y1, y2, N);
    k_propagate_last<<<pg, pb>>>(y2, y1, E0, out, N, NQ);
}

// round 16
// speedup vs baseline: 1.1268x; 1.0423x over previous
#include <cuda_runtime.h>
#include <cuda_fp16.h>
#include <stdint.h>

// ---------------------------------------------------------------------------
// LightGCN: N=100000, D=64, E=1000000, 3 layers.
// out[0:ND] = E0 ; out[ND:2ND] = (E0 + x1 + x2 + x3)/4
//
// y = dinv (.) x stored fp16; x_l = di*s_l, y_l = di^2*s_l, s_l = sum y_{l-1}[src].
// R16 = R15 + (a) software-pipelined src-index prefetch in the propagate loops
// (breaks the src->gather serial chain), (b) warp-shuffle scan (2 barriers
// instead of 20).
// ---------------------------------------------------------------------------

#define MAXN 100000
#define MAXE 1000000
#define D    64
#define PROP_GRID 1184   // 148 SMs x 8 blocks/SM resident

__device__ int    g_deg[MAXN];        // zero at load; re-zeroed in fill_init
__device__ float  g_dinv[MAXN];
__device__ float  g_rdi[MAXN];
__device__ int    g_off[MAXN + 1];
__device__ int    g_cursor[MAXN];
__device__ int    g_blocksums[128];
__device__ int    g_scanflag[128];
__device__ int    g_src[MAXE];
__device__ uint4  g_y0[MAXN * 8];
__device__ uint4  g_y1[MAXN * 8];
__device__ uint4  g_y2[MAXN * 8];

// ---------------------------------------------------------------------------
// Per-block dtype sniff: int64 indices < 2^31 have every odd 32-bit word == 0.
__device__ __forceinline__ bool block_is64(const int* __restrict__ p, int* s_flag) {
    if (threadIdx.x == 0) {
        int nz = 0;
        #pragma unroll 8
        for (int j = 1; j < 256; j += 2) nz += (p[j] != 0);
        *s_flag = (nz == 0);
    }
    __syncthreads();
    return *s_flag != 0;
}

// Histogram of destinations, 4 edges per thread. Block 0 also resets scan flags.
__global__ void k_hist(const void* __restrict__ ei, int E) {
    __shared__ int s64;
    bool is64 = block_is64((const int*)ei, &s64);
    if (blockIdx.x == 0 && threadIdx.x < 128) g_scanflag[threadIdx.x] = 0;
    int base = (blockIdx.x * blockDim.x + threadIdx.x) * 4;
    if (base >= E) return;
    int d0, d1, d2, d3;
    int n = E - base;
    if (is64) {
        const long long* p = (const long long*)ei + E + base;
        if (n >= 4) {
            longlong2 a = ((const longlong2*)p)[0];
            longlong2 b = ((const longlong2*)p)[1];
            d0 = (int)a.x; d1 = (int)a.y; d2 = (int)b.x; d3 = (int)b.y;
        } else {
            d0 = (int)p[0];
            d1 = (n > 1) ? (int)p[1] : -1;
            d2 = (n > 2) ? (int)p[2] : -1;
            d3 = -1;
        }
    } else {
        const int* p = (const int*)ei + E + base;
        if (n >= 4) {
            int4 a = *(const int4*)p;
            d0 = a.x; d1 = a.y; d2 = a.z; d3 = a.w;
        } else {
            d0 = p[0];
            d1 = (n > 1) ? p[1] : -1;
            d2 = (n > 2) ? p[2] : -1;
            d3 = -1;
        }
    }
    atomicAdd(&g_deg[d0], 1);
    if (d1 >= 0) atomicAdd(&g_deg[d1], 1);
    if (d2 >= 0) atomicAdd(&g_deg[d2], 1);
    if (d3 >= 0) atomicAdd(&g_deg[d3], 1);
}

// Single-pass exclusive scan of deg -> off (+ dinv/rdi). Warp-shuffle local
// scan (2 barriers). All 98 blocks resident -> cross-block flag polling safe.
__global__ void k_scan(int N, int E) {
    __shared__ int warpsum[32];
    __shared__ int warpbase[32];
    __shared__ int sh[1024];
    int tid = threadIdx.x;
    int bid = blockIdx.x;
    int lane = tid & 31;
    int wid = tid >> 5;
    int i = bid * 1024 + tid;
    int v = (i < N) ? g_deg[i] : 0;
    if (i < N) {
        float fv = (float)v;
        g_dinv[i] = (v > 0) ? rsqrtf(fv) : 0.0f;
        g_rdi[i]  = (v > 0) ? sqrtf(fv)  : 0.0f;
    }
    // Intra-warp inclusive scan.
    int x = v;
    #pragma unroll
    for (int ofs = 1; ofs < 32; ofs <<= 1) {
        int t = __shfl_up_sync(0xffffffffu, x, ofs);
        if (lane >= ofs) x += t;
    }
    if (lane == 31) warpsum[wid] = x;
    __syncthreads();
    // One warp scans the 32 warp sums (exclusive).
    if (wid == 0) {
        int w = warpsum[lane];
        int xs = w;
        #pragma unroll
        for (int ofs = 1; ofs < 32; ofs <<= 1) {
            int t = __shfl_up_sync(0xffffffffu, xs, ofs);
            if (lane >= ofs) xs += t;
        }
        warpbase[lane] = xs - w;
    }
    __syncthreads();
    int incl = x + warpbase[wid];
    // Publish block aggregate with release semantics.
    if (tid == 1023) {
        g_blocksums[bid] = incl;
        __threadfence();
        ((volatile int*)g_scanflag)[bid] = 1;
    }
    __syncthreads();
    // Poll all predecessors' aggregates in parallel, then tree-reduce.
    int part = 0;
    if (tid < bid) {
        while (((volatile int*)g_scanflag)[tid] == 0) {}
        __threadfence();
        part = g_blocksums[tid];
    }
    sh[tid] = part;
    __syncthreads();
    #pragma unroll
    for (int ofs = 512; ofs > 0; ofs >>= 1) {
        if (tid < ofs) sh[tid] += sh[tid + ofs];
        __syncthreads();
    }
    int base = sh[0];
    if (i < N) {
        int o = base + incl - v;
        g_off[i] = o;
        g_cursor[i] = o;
    }
    if (i == 0) g_off[N] = E;
}

// Fused: CSR fill (atomic cursor, 1 edge/thread) + out[0:NQ]=E0 + y0 init
// + deg reset. (R12/R15 exact arrangement.)
__global__ void k_fill_init(const void* __restrict__ ei,
                            const float4* __restrict__ E0,
                            float4* __restrict__ out,
                            int E, int NQ, int N) {
    __shared__ int s64;
    bool is64 = block_is64((const int*)ei, &s64);
    int i = blockIdx.x * blockDim.x + threadIdx.x;
    if (i < N) g_deg[i] = 0;
    if (i < E) {
        int s, d;
        if (is64) {
            s = (int)((const long long*)ei)[i];
            d = (int)((const long long*)ei)[E + i];
        } else {
            s = ((const int*)ei)[i];
            d = ((const int*)ei)[E + i];
        }
        int pos = atomicAdd(&g_cursor[d], 1);
        g_src[pos] = s;
    }
    if (i < NQ) {
        float4 v = E0[i];
        out[i] = v;
        float di = g_dinv[i >> 4];
        uint2 w;
        __half2* hw = (__half2*)&w;
        hw[0] = __floats2half2_rn(v.x * di, v.y * di);
        hw[1] = __floats2half2_rn(v.z * di, v.w * di);
        ((uint2*)g_y0)[i] = w;
    }
}

// Mid-layer propagate: persistent grid-stride; 8 lanes/node, 2-edge unroll,
// 2 HADD2 banks, 8 blocks/SM. Src indices PREFETCHED one iteration ahead so
// the per-iteration critical path is the row gather only.
__global__ void __launch_bounds__(256, 8)
k_propagate(const uint4* __restrict__ y, uint4* __restrict__ yn, int N) {
    int t = threadIdx.x;  // 0..7
    int stride = gridDim.x * 32;
    for (int node = blockIdx.x * 32 + threadIdx.y; node < N; node += stride) {
        int beg = g_off[node];
        int end = g_off[node + 1];
        __half2 z = __float2half2_rn(0.f);
        __half2 a0[4] = {z, z, z, z};
        __half2 a1[4] = {z, z, z, z};
        int e = beg;
        if (end - beg >= 2) {
            int sa = g_src[e];
            int sb = g_src[e + 1];
            for (; e + 3 < end; e += 2) {
                int sa_n = g_src[e + 2];
                int sb_n = g_src[e + 3];
                uint4 ua = y[sa * 8 + t];
                uint4 ub = y[sb * 8 + t];
                const __half2* ha = (const __half2*)&ua;
                const __half2* hb = (const __half2*)&ub;
                #pragma unroll
                for (int j = 0; j < 4; j++) {
                    a0[j] = __hadd2(a0[j], ha[j]);
                    a1[j] = __hadd2(a1[j], hb[j]);
                }
                sa = sa_n; sb = sb_n;
            }
            // Drain the prefetched pair.
            {
                uint4 ua = y[sa * 8 + t];
                uint4 ub = y[sb * 8 + t];
                const __half2* ha = (const __half2*)&ua;
                const __half2* hb = (const __half2*)&ub;
                #pragma unroll
                for (int j = 0; j < 4; j++) {
                    a0[j] = __hadd2(a0[j], ha[j]);
                    a1[j] = __hadd2(a1[j], hb[j]);
                }
                e += 2;
            }
        }
        for (; e < end; e++) {
            uint4 ua = y[g_src[e] * 8 + t];
            const __half2* ha = (const __half2*)&ua;
            #pragma unroll
            for (int j = 0; j < 4; j++) a0[j] = __hadd2(a0[j], ha[j]);
        }
        float di2 = g_dinv[node];
        di2 *= di2;
        uint4 w;
        __half2* hw = (__half2*)&w;
        #pragma unroll
        for (int j = 0; j < 4; j++) {
            float2 f0 = __half22float2(a0[j]);
            float2 f1 = __half22float2(a1[j]);
            hw[j] = __floats2half2_rn(di2 * (f0.x + f1.x), di2 * (f0.y + f1.y));
        }
        yn[node * 8 + t] = w;
    }
}

// Final layer fused with output: persistent grid-stride, prefetched src,
// 2-bank HADD2 gather, fp32 finalize. out = 0.25*(E0 + (y1+y2)*rdi + di*s3).
__global__ void __launch_bounds__(256, 8)
k_propagate_last(const uint4* __restrict__ y2,
                 const uint4* __restrict__ y1,
                 const float4* __restrict__ E0,
                 float4* __restrict__ out, int N, int NQ) {
    int t = threadIdx.x;
    int stride = gridDim.x * 32;
    for (int node = blockIdx.x * 32 + threadIdx.y; node < N; node += stride) {
        int beg = g_off[node];
        int end = g_off[node + 1];
        __half2 z = __float2half2_rn(0.f);
        __half2 a0[4] = {z, z, z, z};
        __half2 a1[4] = {z, z, z, z};
        int e = beg;
        if (end - beg >= 2) {
            int sa = g_src[e];
            int sb = g_src[e + 1];
            for (; e + 3 < end; e += 2) {
                int sa_n = g_src[e + 2];
                int sb_n = g_src[e + 3];
                uint4 ua = y2[sa * 8 + t];
                uint4 ub = y2[sb * 8 + t];
                const __half2* ha = (const __half2*)&ua;
                const __half2* hb = (const __half2*)&ub;
                #pragma unroll
                for (int j = 0; j < 4; j++) {
                    a0[j] = __hadd2(a0[j], ha[j]);
                    a1[j] = __hadd2(a1[j], hb[j]);
                }
                sa = sa_n; sb = sb_n;
            }
            {
                uint4 ua = y2[sa * 8 + t];
                uint4 ub = y2[sb * 8 + t];
                const __half2* ha = (const __half2*)&ua;
                const __half2* hb = (const __half2*)&ub;
                #pragma unroll
                for (int j = 0; j < 4; j++) {
                    a0[j] = __hadd2(a0[j], ha[j]);
                    a1[j] = __hadd2(a1[j], hb[j]);
                }
                e += 2;
            }
        }
        for (; e < end; e++) {
            uint4 ua = y2[g_src[e] * 8 + t];
            const __half2* ha = (const __half2*)&ua;
            #pragma unroll
            for (int j = 0; j < 4; j++) a0[j] = __hadd2(a0[j], ha[j]);
        }
        float di  = g_dinv[node];
        float rdi = g_rdi[node];

        uint4 u1 = y1[node * 8 + t];
        uint4 u2 = y2[node * 8 + t];
        const __half2* h1 = (const __half2*)&u1;
        const __half2* h2 = (const __half2*)&u2;

        int o4 = node * 16 + t * 2;
        float4 e0a = E0[o4], e0b = E0[o4 + 1];
        float rr[8];
        #pragma unroll
        for (int j = 0; j < 4; j++) {
            float2 f0 = __half22float2(a0[j]);
            float2 f1 = __half22float2(a1[j]);
            float2 g1 = __half22float2(h1[j]);
            float2 g2 = __half22float2(h2[j]);
            rr[2 * j]     = rdi * (g1.x + g2.x) + di * (f0.x + f1.x);
            rr[2 * j + 1] = rdi * (g1.y + g2.y) + di * (f0.y + f1.y);
        }
        float4 r0, r1;
        r0.x = 0.25f * (e0a.x + rr[0]);
        r0.y = 0.25f * (e0a.y + rr[1]);
        r0.z = 0.25f * (e0a.z + rr[2]);
        r0.w = 0.25f * (e0a.w + rr[3]);
        r1.x = 0.25f * (e0b.x + rr[4]);
        r1.y = 0.25f * (e0b.y + rr[5]);
        r1.z = 0.25f * (e0b.z + rr[6]);
        r1.w = 0.25f * (e0b.w + rr[7]);
        out[NQ + o4] = r0;
        out[NQ + o4 + 1] = r1;
    }
}

// ---------------------------------------------------------------------------

extern "C" void kernel_launch(void* const* d_in, const int* in_sizes, int n_in,
                              void* d_out, int out_size) {
    const float4* E0 = (const float4*)d_in[0];
    const void*   ei = d_in[1];
    float4*       out = (float4*)d_out;

    int N  = in_sizes[0] / D;   // 100000
    int E  = in_sizes[1] / 2;   // 1000000
    int NQ = N * 16;

    void *p0 = nullptr, *p1 = nullptr, *p2 = nullptr;
    cudaGetSymbolAddress(&p0, g_y0);
    cudaGetSymbolAddress(&p1, g_y1);
    cudaGetSymbolAddress(&p2, g_y2);
    uint4* y0 = (uint4*)p0;
    uint4* y1 = (uint4*)p1;
    uint4* y2 = (uint4*)p2;

    const int T = 256;
    int nb_scan = (N + 1023) / 1024;
    int nb_hist = ((E + 3) / 4 + T - 1) / T;

    k_hist<<<nb_hist, T>>>(ei, E);
    k_scan<<<nb_scan, 1024>>>(N, E);
    k_fill_init<<<(NQ + T - 1) / T, T>>>(ei, E0, out, E, NQ, N);

    dim3 pb(8, 32);
    int  pg_full = (N + 31) / 32;
    int  pg = pg_full < PROP_GRID ? pg_full : PROP_GRID;
    k_propagate<<<pg, pb>>>(y0, y1, N);
    k_propagate<<<pg, pb>>>(y1, y2, N);
    k_propagate_last<<<pg, pb>>>(y2, y1, E0, out, N, NQ);
}

// round 17
// speedup vs baseline: 1.1291x; 1.0021x over previous
#include <cuda_runtime.h>
#include <cuda_fp16.h>
#include <stdint.h>

// ---------------------------------------------------------------------------
// LightGCN: N=100000, D=64, E=1000000, 3 layers.
// out[0:ND] = E0 ; out[ND:2ND] = (E0 + x1 + x2 + x3)/4
//
// y = dinv (.) x stored fp16; x_l = di*s_l, y_l = di^2*s_l, s_l = sum y_{l-1}[src].
// R17 = R16 + evict-first (__stcs) stores for ALL `out` writes: out (51MB,
// write-once) no longer thrashes L2, keeping edges/E0/y L2-resident across
// kernels and graph replays.
// ---------------------------------------------------------------------------

#define MAXN 100000
#define MAXE 1000000
#define D    64
#define PROP_GRID 1184   // 148 SMs x 8 blocks/SM resident

__device__ int    g_deg[MAXN];        // zero at load; re-zeroed in fill_init
__device__ float  g_dinv[MAXN];
__device__ float  g_rdi[MAXN];
__device__ int    g_off[MAXN + 1];
__device__ int    g_cursor[MAXN];
__device__ int    g_blocksums[128];
__device__ int    g_scanflag[128];
__device__ int    g_src[MAXE];
__device__ uint4  g_y0[MAXN * 8];
__device__ uint4  g_y1[MAXN * 8];
__device__ uint4  g_y2[MAXN * 8];

// ---------------------------------------------------------------------------
// Per-block dtype sniff: int64 indices < 2^31 have every odd 32-bit word == 0.
__device__ __forceinline__ bool block_is64(const int* __restrict__ p, int* s_flag) {
    if (threadIdx.x == 0) {
        int nz = 0;
        #pragma unroll 8
        for (int j = 1; j < 256; j += 2) nz += (p[j] != 0);
        *s_flag = (nz == 0);
    }
    __syncthreads();
    return *s_flag != 0;
}

// Histogram of destinations, 4 edges per thread. Block 0 also resets scan flags.
__global__ void k_hist(const void* __restrict__ ei, int E) {
    __shared__ int s64;
    bool is64 = block_is64((const int*)ei, &s64);
    if (blockIdx.x == 0 && threadIdx.x < 128) g_scanflag[threadIdx.x] = 0;
    int base = (blockIdx.x * blockDim.x + threadIdx.x) * 4;
    if (base >= E) return;
    int d0, d1, d2, d3;
    int n = E - base;
    if (is64) {
        const long long* p = (const long long*)ei + E + base;
        if (n >= 4) {
            longlong2 a = ((const longlong2*)p)[0];
            longlong2 b = ((const longlong2*)p)[1];
            d0 = (int)a.x; d1 = (int)a.y; d2 = (int)b.x; d3 = (int)b.y;
        } else {
            d0 = (int)p[0];
            d1 = (n > 1) ? (int)p[1] : -1;
            d2 = (n > 2) ? (int)p[2] : -1;
            d3 = -1;
        }
    } else {
        const int* p = (const int*)ei + E + base;
        if (n >= 4) {
            int4 a = *(const int4*)p;
            d0 = a.x; d1 = a.y; d2 = a.z; d3 = a.w;
        } else {
            d0 = p[0];
            d1 = (n > 1) ? p[1] : -1;
            d2 = (n > 2) ? p[2] : -1;
            d3 = -1;
        }
    }
    atomicAdd(&g_deg[d0], 1);
    if (d1 >= 0) atomicAdd(&g_deg[d1], 1);
    if (d2 >= 0) atomicAdd(&g_deg[d2], 1);
    if (d3 >= 0) atomicAdd(&g_deg[d3], 1);
}

// Single-pass exclusive scan of deg -> off (+ dinv/rdi). Warp-shuffle local
// scan (2 barriers). All 98 blocks resident -> cross-block flag polling safe.
__global__ void k_scan(int N, int E) {
    __shared__ int warpsum[32];
    __shared__ int warpbase[32];
    __shared__ int sh[1024];
    int tid = threadIdx.x;
    int bid = blockIdx.x;
    int lane = tid & 31;
    int wid = tid >> 5;
    int i = bid * 1024 + tid;
    int v = (i < N) ? g_deg[i] : 0;
    if (i < N) {
        float fv = (float)v;
        g_dinv[i] = (v > 0) ? rsqrtf(fv) : 0.0f;
        g_rdi[i]  = (v > 0) ? sqrtf(fv)  : 0.0f;
    }
    int x = v;
    #pragma unroll
    for (int ofs = 1; ofs < 32; ofs <<= 1) {
        int t = __shfl_up_sync(0xffffffffu, x, ofs);
        if (lane >= ofs) x += t;
    }
    if (lane == 31) warpsum[wid] = x;
    __syncthreads();
    if (wid == 0) {
        int w = warpsum[lane];
        int xs = w;
        #pragma unroll
        for (int ofs = 1; ofs < 32; ofs <<= 1) {
            int t = __shfl_up_sync(0xffffffffu, xs, ofs);
            if (lane >= ofs) xs += t;
        }
        warpbase[lane] = xs - w;
    }
    __syncthreads();
    int incl = x + warpbase[wid];
    if (tid == 1023) {
        g_blocksums[bid] = incl;
        __threadfence();
        ((volatile int*)g_scanflag)[bid] = 1;
    }
    __syncthreads();
    int part = 0;
    if (tid < bid) {
        while (((volatile int*)g_scanflag)[tid] == 0) {}
        __threadfence();
        part = g_blocksums[tid];
    }
    sh[tid] = part;
    __syncthreads();
    #pragma unroll
    for (int ofs = 512; ofs > 0; ofs >>= 1) {
        if (tid < ofs) sh[tid] += sh[tid + ofs];
        __syncthreads();
    }
    int base = sh[0];
    if (i < N) {
        int o = base + incl - v;
        g_off[i] = o;
        g_cursor[i] = o;
    }
    if (i == 0) g_off[N] = E;
}

// Fused: CSR fill (atomic cursor, 1 edge/thread) + out[0:NQ]=E0 (evict-first)
// + y0 init + deg reset.
__global__ void k_fill_init(const void* __restrict__ ei,
                            const float4* __restrict__ E0,
                            float4* __restrict__ out,
                            int E, int NQ, int N) {
    __shared__ int s64;
    bool is64 = block_is64((const int*)ei, &s64);
    int i = blockIdx.x * blockDim.x + threadIdx.x;
    if (i < N) g_deg[i] = 0;
    if (i < E) {
        int s, d;
        if (is64) {
            s = (int)((const long long*)ei)[i];
            d = (int)((const long long*)ei)[E + i];
        } else {
            s = ((const int*)ei)[i];
            d = ((const int*)ei)[E + i];
        }
        int pos = atomicAdd(&g_cursor[d], 1);
        g_src[pos] = s;
    }
    if (i < NQ) {
        float4 v = E0[i];
        __stcs(&out[i], v);   // evict-first: out is write-once
        float di = g_dinv[i >> 4];
        uint2 w;
        __half2* hw = (__half2*)&w;
        hw[0] = __floats2half2_rn(v.x * di, v.y * di);
        hw[1] = __floats2half2_rn(v.z * di, v.w * di);
        ((uint2*)g_y0)[i] = w;
    }
}

// Mid-layer propagate: persistent grid-stride; 8 lanes/node, 2-edge unroll,
// 2 HADD2 banks, 8 blocks/SM, src indices prefetched one iteration ahead.
__global__ void __launch_bounds__(256, 8)
k_propagate(const uint4* __restrict__ y, uint4* __restrict__ yn, int N) {
    int t = threadIdx.x;  // 0..7
    int stride = gridDim.x * 32;
    for (int node = blockIdx.x * 32 + threadIdx.y; node < N; node += stride) {
        int beg = g_off[node];
        int end = g_off[node + 1];
        __half2 z = __float2half2_rn(0.f);
        __half2 a0[4] = {z, z, z, z};
        __half2 a1[4] = {z, z, z, z};
        int e = beg;
        if (end - beg >= 2) {
            int sa = g_src[e];
            int sb = g_src[e + 1];
            for (; e + 3 < end; e += 2) {
                int sa_n = g_src[e + 2];
                int sb_n = g_src[e + 3];
                uint4 ua = y[sa * 8 + t];
                uint4 ub = y[sb * 8 + t];
                const __half2* ha = (const __half2*)&ua;
                const __half2* hb = (const __half2*)&ub;
                #pragma unroll
                for (int j = 0; j < 4; j++) {
                    a0[j] = __hadd2(a0[j], ha[j]);
                    a1[j] = __hadd2(a1[j], hb[j]);
                }
                sa = sa_n; sb = sb_n;
            }
            {
                uint4 ua = y[sa * 8 + t];
                uint4 ub = y[sb * 8 + t];
                const __half2* ha = (const __half2*)&ua;
                const __half2* hb = (const __half2*)&ub;
                #pragma unroll
                for (int j = 0; j < 4; j++) {
                    a0[j] = __hadd2(a0[j], ha[j]);
                    a1[j] = __hadd2(a1[j], hb[j]);
                }
                e += 2;
            }
        }
        for (; e < end; e++) {
            uint4 ua = y[g_src[e] * 8 + t];
            const __half2* ha = (const __half2*)&ua;
            #pragma unroll
            for (int j = 0; j < 4; j++) a0[j] = __hadd2(a0[j], ha[j]);
        }
        float di2 = g_dinv[node];
        di2 *= di2;
        uint4 w;
        __half2* hw = (__half2*)&w;
        #pragma unroll
        for (int j = 0; j < 4; j++) {
            float2 f0 = __half22float2(a0[j]);
            float2 f1 = __half22float2(a1[j]);
            hw[j] = __floats2half2_rn(di2 * (f0.x + f1.x), di2 * (f0.y + f1.y));
        }
        yn[node * 8 + t] = w;
    }
}

// Final layer fused with output: persistent grid-stride, prefetched src,
// 2-bank HADD2 gather, fp32 finalize, evict-first out stores.
__global__ void __launch_bounds__(256, 8)
k_propagate_last(const uint4* __restrict__ y2,
                 const uint4* __restrict__ y1,
                 const float4* __restrict__ E0,
                 float4* __restrict__ out, int N, int NQ) {
    int t = threadIdx.x;
    int stride = gridDim.x * 32;
    for (int node = blockIdx.x * 32 + threadIdx.y; node < N; node += stride) {
        int beg = g_off[node];
        int end = g_off[node + 1];
        __half2 z = __float2half2_rn(0.f);
        __half2 a0[4] = {z, z, z, z};
        __half2 a1[4] = {z, z, z, z};
        int e = beg;
        if (end - beg >= 2) {
            int sa = g_src[e];
            int sb = g_src[e + 1];
            for (; e + 3 < end; e += 2) {
                int sa_n = g_src[e + 2];
                int sb_n = g_src[e + 3];
                uint4 ua = y2[sa * 8 + t];
                uint4 ub = y2[sb * 8 + t];
                const __half2* ha = (const __half2*)&ua;
                const __half2* hb = (const __half2*)&ub;
                #pragma unroll
                for (int j = 0; j < 4; j++) {
                    a0[j] = __hadd2(a0[j], ha[j]);
                    a1[j] = __hadd2(a1[j], hb[j]);
                }
                sa = sa_n; sb = sb_n;
            }
            {
                uint4 ua = y2[sa * 8 + t];
                uint4 ub = y2[sb * 8 + t];
                const __half2* ha = (const __half2*)&ua;
                const __half2* hb = (const __half2*)&ub;
                #pragma unroll
                for (int j = 0; j < 4; j++) {
                    a0[j] = __hadd2(a0[j], ha[j]);
                    a1[j] = __hadd2(a1[j], hb[j]);
                }
                e += 2;
            }
        }
        for (; e < end; e++) {
            uint4 ua = y2[g_src[e] * 8 + t];
            const __half2* ha = (const __half2*)&ua;
            #pragma unroll
            for (int j = 0; j < 4; j++) a0[j] = __hadd2(a0[j], ha[j]);
        }
        float di  = g_dinv[node];
        float rdi = g_rdi[node];

        uint4 u1 = y1[node * 8 + t];
        uint4 u2 = y2[node * 8 + t];
        const __half2* h1 = (const __half2*)&u1;
        const __half2* h2 = (const __half2*)&u2;

        int o4 = node * 16 + t * 2;
        float4 e0a = E0[o4], e0b = E0[o4 + 1];
        float rr[8];
        #pragma unroll
        for (int j = 0; j < 4; j++) {
            float2 f0 = __half22float2(a0[j]);
            float2 f1 = __half22float2(a1[j]);
            float2 g1 = __half22float2(h1[j]);
            float2 g2 = __half22float2(h2[j]);
            rr[2 * j]     = rdi * (g1.x + g2.x) + di * (f0.x + f1.x);
            rr[2 * j + 1] = rdi * (g1.y + g2.y) + di * (f0.y + f1.y);
        }
        float4 r0, r1;
        r0.x = 0.25f * (e0a.x + rr[0]);
        r0.y = 0.25f * (e0a.y + rr[1]);
        r0.z = 0.25f * (e0a.z + rr[2]);
        r0.w = 0.25f * (e0a.w + rr[3]);
        r1.x = 0.25f * (e0b.x + rr[4]);
        r1.y = 0.25f * (e0b.y + rr[5]);
        r1.z = 0.25f * (e0b.z + rr[6]);
        r1.w = 0.25f * (e0b.w + rr[7]);
        __stcs(&out[NQ + o4], r0);       // evict-first: write-once output
        __stcs(&out[NQ + o4 + 1], r1);
    }
}

// ---------------------------------------------------------------------------

extern "C" void kernel_launch(void* const* d_in, const int* in_sizes, int n_in,
                              void* d_out, int out_size) {
    const float4* E0 = (const float4*)d_in[0];
    const void*   ei = d_in[1];
    float4*       out = (float4*)d_out;

    int N  = in_sizes[0] / D;   // 100000
    int E  = in_sizes[1] / 2;   // 1000000
    int NQ = N * 16;

    void *p0 = nullptr, *p1 = nullptr, *p2 = nullptr;
    cudaGetSymbolAddress(&p0, g_y0);
    cudaGetSymbolAddress(&p1, g_y1);
    cudaGetSymbolAddress(&p2, g_y2);
    uint4* y0 = (uint4*)p0;
    uint4* y1 = (uint4*)p1;
    uint4* y2 = (uint4*)p2;

    const int T = 256;
    int nb_scan = (N + 1023) / 1024;
    int nb_hist = ((E + 3) / 4 + T - 1) / T;

    k_hist<<<nb_hist, T>>>(ei, E);
    k_scan<<<nb_scan, 1024>>>(N, E);
    k_fill_init<<<(NQ + T - 1) / T, T>>>(ei, E0, out, E, NQ, N);

    dim3 pb(8, 32);
    int  pg_full = (N + 31) / 32;
    int  pg = pg_full < PROP_GRID ? pg_full : PROP_GRID;
    k_propagate<<<pg, pb>>>(y0, y1, N);
    k_propagate<<<pg, pb>>>(y1, y2, N);
    k_propagate_last<<<pg, pb>>>(y2, y1, E0, out, N, NQ);
}